// round 1
// baseline (speedup 1.0000x reference)
#include <cuda_runtime.h>
#include <cstdint>
#include <cstddef>

// Problem dims (fixed by the dataset)
#define E_DIM 16
#define B_DIM 128
#define C_DIM 512
#define H_DIM 1024
#define D_DIM 130
#define S_DIM 16
#define NROW  2048            // E*B
#define G3    3072            // 3*H
#define TROW  32768           // S*NROW
#define OUT_T 256             // E*S_DIM

// ---------------- scratch (static device globals; no allocation) -------------
__device__ float g_H1[NROW * H_DIM];
__device__ float g_H2[NROW * H_DIM];
__device__ float g_TA[NROW * G3];
__device__ float g_TB[NROW * G3];
__device__ float g_CP[NROW * G3];
__device__ float g_T0[NROW * 2 * H_DIM];
__device__ float g_PREV[(size_t)S_DIM * NROW * D_DIM];
__device__ float g_PP[(size_t)S_DIM * NROW * G3];      // prevpart, all steps
__device__ float g_HA[(size_t)S_DIM * NROW * H_DIM];   // h2 history
__device__ float g_Y[(size_t)TROW * D_DIM];

// ---------------- TF32 mma helpers ------------------------------------------
__device__ __forceinline__ unsigned f2tf32(float x) {
    unsigned r;
    asm("cvt.rna.tf32.f32 %0, %1;" : "=r"(r) : "f"(x));
    return r;
}

__device__ __forceinline__ void mma_tf32(float d[4], const unsigned a[4],
                                         const unsigned b[2]) {
    asm volatile(
        "mma.sync.aligned.m16n8k8.row.col.f32.tf32.tf32.f32 "
        "{%0,%1,%2,%3}, {%4,%5,%6,%7}, {%8,%9}, {%0,%1,%2,%3};\n"
        : "+f"(d[0]), "+f"(d[1]), "+f"(d[2]), "+f"(d[3])
        : "r"(a[0]), "r"(a[1]), "r"(a[2]), "r"(a[3]),
          "r"(b[0]), "r"(b[1]));
}

// ---------------- generic TN GEMM: C[M,N] = A[M,K] * B[N,K]^T (+bias[n]) -----
// BM=BN=128, BK=32, 256 threads, 8 warps in 2(m) x 4(n), warp tile 64x32.
#define BM 128
#define BN 128
#define BK 32
#define SPAD 4   // smem row stride 36 -> conflict-free for STS and frag LDS

template <bool HAS_BIAS>
__global__ __launch_bounds__(256, 2) void gemm_tn(
    const float* __restrict__ A, int lda,
    const float* __restrict__ B, int ldb,
    const float* __restrict__ bias,
    float* __restrict__ C, int ldc,
    int M, int N, int K)
{
    __shared__ float As[BM][BK + SPAD];
    __shared__ float Bs[BN][BK + SPAD];

    const int tid  = threadIdx.x;
    const int lane = tid & 31;
    const int warp = tid >> 5;
    const int wm   = (warp & 1) * 64;   // warp m-offset in block tile
    const int wn   = (warp >> 1) * 32;  // warp n-offset in block tile
    const int g    = lane >> 2;         // groupID
    const int tg   = lane & 3;          // threadID_in_group

    const int bm0 = blockIdx.y * BM;
    const int bn0 = blockIdx.x * BN;

    float acc[4][4][4];
#pragma unroll
    for (int mi = 0; mi < 4; mi++)
#pragma unroll
        for (int ni = 0; ni < 4; ni++)
#pragma unroll
            for (int f = 0; f < 4; f++) acc[mi][ni][f] = 0.f;

    for (int kt = 0; kt < K; kt += BK) {
        // ---- load tiles (coalesced rows of 32 floats) ----
#pragma unroll
        for (int i = 0; i < 16; i++) {
            int idx = i * 256 + tid;
            int r = idx >> 5, cc = idx & 31;
            int gr = bm0 + r, gc = kt + cc;
            As[r][cc] = (gr < M && gc < K) ? A[(size_t)gr * lda + gc] : 0.f;
        }
#pragma unroll
        for (int i = 0; i < 16; i++) {
            int idx = i * 256 + tid;
            int r = idx >> 5, cc = idx & 31;
            int gr = bn0 + r, gc = kt + cc;
            Bs[r][cc] = (gr < N && gc < K) ? B[(size_t)gr * ldb + gc] : 0.f;
        }
        __syncthreads();

#pragma unroll
        for (int ks = 0; ks < BK / 8; ks++) {
            const int k0 = ks * 8;
            unsigned af[4][4], bf[4][2];
#pragma unroll
            for (int mi = 0; mi < 4; mi++) {
                const int rb = wm + mi * 16;
                af[mi][0] = f2tf32(As[rb + g][k0 + tg]);
                af[mi][1] = f2tf32(As[rb + g + 8][k0 + tg]);
                af[mi][2] = f2tf32(As[rb + g][k0 + tg + 4]);
                af[mi][3] = f2tf32(As[rb + g + 8][k0 + tg + 4]);
            }
#pragma unroll
            for (int ni = 0; ni < 4; ni++) {
                const int nb = wn + ni * 8;
                bf[ni][0] = f2tf32(Bs[nb + g][k0 + tg]);
                bf[ni][1] = f2tf32(Bs[nb + g][k0 + tg + 4]);
            }
#pragma unroll
            for (int mi = 0; mi < 4; mi++)
#pragma unroll
                for (int ni = 0; ni < 4; ni++)
                    mma_tf32(acc[mi][ni], af[mi], bf[ni]);
        }
        __syncthreads();
    }

    // ---- epilogue: C[m][n] = acc (+ bias) ----
#pragma unroll
    for (int mi = 0; mi < 4; mi++) {
        const int r0 = bm0 + wm + mi * 16 + g;
#pragma unroll
        for (int ni = 0; ni < 4; ni++) {
            const int c0 = bn0 + wn + ni * 8 + 2 * tg;
            float b0 = 0.f, b1 = 0.f;
            if (HAS_BIAS) {
                if (c0 < N)     b0 = bias[c0];
                if (c0 + 1 < N) b1 = bias[c0 + 1];
            }
            if (r0 < M) {
                if (c0 < N)     C[(size_t)r0 * ldc + c0]     = acc[mi][ni][0] + b0;
                if (c0 + 1 < N) C[(size_t)r0 * ldc + c0 + 1] = acc[mi][ni][1] + b1;
            }
            if (r0 + 8 < M) {
                if (c0 < N)     C[(size_t)(r0 + 8) * ldc + c0]     = acc[mi][ni][2] + b0;
                if (c0 + 1 < N) C[(size_t)(r0 + 8) * ldc + c0 + 1] = acc[mi][ni][3] + b1;
            }
        }
    }
}

// ---------------- elementwise kernels ----------------------------------------
// GRU gate fusion: gi = gi1 (+gi2), gh already has bhh; h' = (1-z)*n + z*h
__global__ void gate_kernel(const float* __restrict__ gi1,
                            const float* __restrict__ gi2,
                            const float* __restrict__ gh,
                            float* __restrict__ h,
                            float* __restrict__ hcopy)
{
    int idx = blockIdx.x * blockDim.x + threadIdx.x;  // exactly NROW*H
    int m = idx >> 10, j = idx & 1023;
    size_t base = (size_t)m * G3 + j;
    float ir = gi1[base], iz = gi1[base + H_DIM], in = gi1[base + 2 * H_DIM];
    if (gi2 != nullptr) {
        ir += gi2[base];
        iz += gi2[base + H_DIM];
        in += gi2[base + 2 * H_DIM];
    }
    float hr = gh[base], hz = gh[base + H_DIM], hn = gh[base + 2 * H_DIM];
    float r = 1.f / (1.f + __expf(-(ir + hr)));
    float z = 1.f / (1.f + __expf(-(iz + hz)));
    float n = tanhf(in + r * hn);
    float hv = h[idx];
    float outv = (1.f - z) * n + z * hv;
    h[idx] = outv;
    if (hcopy != nullptr) hcopy[idx] = outv;
}

__global__ void init_tanh(const float* __restrict__ t0,
                          float* __restrict__ h1, float* __restrict__ h2)
{
    int idx = blockIdx.x * blockDim.x + threadIdx.x;  // exactly NROW*H
    int m = idx >> 10, j = idx & 1023;
    h1[idx] = tanhf(t0[(size_t)m * (2 * H_DIM) + j]);
    h2[idx] = tanhf(t0[(size_t)m * (2 * H_DIM) + H_DIM + j]);
}

// PREV[s, e*B+b, d] = (global t==0) ? 0 : target[b, t-1, d], t = e*S + s
__global__ void pack_prev(const float* __restrict__ target,
                          float* __restrict__ prev)
{
    int idx = blockIdx.x * blockDim.x + threadIdx.x;
    if (idx >= S_DIM * NROW * D_DIM) return;
    int d = idx % D_DIM;
    int r = (idx / D_DIM) % NROW;
    int s = idx / (D_DIM * NROW);
    int e = r >> 7, b = r & 127;
    int t = e * S_DIM + s;
    prev[idx] = (t == 0) ? 0.f
                         : target[((size_t)b * OUT_T + (t - 1)) * D_DIM + d];
}

// out[b, e*S+s, d] = Y[s*NROW + e*B + b, d]
__global__ void scatter_out(const float* __restrict__ y,
                            float* __restrict__ out)
{
    int idx = blockIdx.x * blockDim.x + threadIdx.x;
    if (idx >= TROW * D_DIM) return;
    int d = idx % D_DIM;
    int m = idx / D_DIM;
    int s = m >> 11;
    int r = m & 2047;
    int e = r >> 7, b = r & 127;
    out[((size_t)b * OUT_T + e * S_DIM + s) * D_DIM + d] = y[idx];
}

// ---------------- launch helpers ---------------------------------------------
static inline void gemm(const float* A, int lda, const float* B, int ldb,
                        const float* bias, float* C, int ldc,
                        int M, int N, int K)
{
    dim3 grid((N + BN - 1) / BN, (M + BM - 1) / BM);
    if (bias)
        gemm_tn<true><<<grid, 256>>>(A, lda, B, ldb, bias, C, ldc, M, N, K);
    else
        gemm_tn<false><<<grid, 256>>>(A, lda, B, ldb, nullptr, C, ldc, M, N, K);
}

extern "C" void kernel_launch(void* const* d_in, const int* in_sizes, int n_in,
                              void* d_out, int out_size)
{
    const float* c      = (const float*)d_in[0];
    const float* target = (const float*)d_in[1];
    // scalars (length, batch_size) may or may not appear as buffers
    int base = (n_in >= 16) ? 4 : 2;
    const float* fc_init_w = (const float*)d_in[base + 0];
    const float* fc_init_b = (const float*)d_in[base + 1];
    const float* g1_wih    = (const float*)d_in[base + 2];
    const float* g1_whh    = (const float*)d_in[base + 3];
    const float* g1_bih    = (const float*)d_in[base + 4];
    const float* g1_bhh    = (const float*)d_in[base + 5];
    const float* g2_wih    = (const float*)d_in[base + 6];
    const float* g2_whh    = (const float*)d_in[base + 7];
    const float* g2_bih    = (const float*)d_in[base + 8];
    const float* g2_bhh    = (const float*)d_in[base + 9];
    const float* fco_w     = (const float*)d_in[base + 10];
    const float* fco_b     = (const float*)d_in[base + 11];
    float* out = (float*)d_out;

    float *H1, *H2, *TA, *TB, *CP, *T0, *PV, *PP, *HA, *Y;
    cudaGetSymbolAddress((void**)&H1, g_H1);
    cudaGetSymbolAddress((void**)&H2, g_H2);
    cudaGetSymbolAddress((void**)&TA, g_TA);
    cudaGetSymbolAddress((void**)&TB, g_TB);
    cudaGetSymbolAddress((void**)&CP, g_CP);
    cudaGetSymbolAddress((void**)&T0, g_T0);
    cudaGetSymbolAddress((void**)&PV, g_PREV);
    cudaGetSymbolAddress((void**)&PP, g_PP);
    cudaGetSymbolAddress((void**)&HA, g_HA);
    cudaGetSymbolAddress((void**)&Y,  g_Y);

    // ---- precompute (non-recurrent) ----
    pack_prev<<<(S_DIM * NROW * D_DIM + 255) / 256, 256>>>(target, PV);

    // cpart = cflat @ g1_wih[:, :C]^T + g1_bih        [2048 x 3072]
    gemm(c, C_DIM, g1_wih, C_DIM + D_DIM, g1_bih, CP, G3, NROW, G3, C_DIM);
    // prevpart[s] = PREV[s] @ g1_wih[:, C:]^T          [32768 x 3072]
    gemm(PV, D_DIM, g1_wih + C_DIM, C_DIM + D_DIM, nullptr, PP, G3,
         TROW, G3, D_DIM);
    // t0 = c @ fc_init_w^T + fc_init_b                 [2048 x 2048]
    gemm(c, C_DIM, fc_init_w, C_DIM, fc_init_b, T0, 2 * H_DIM,
         NROW, 2 * H_DIM, C_DIM);
    init_tanh<<<(NROW * H_DIM) / 256, 256>>>(T0, H1, H2);

    // ---- recurrent loop ----
    for (int s = 0; s < S_DIM; s++) {
        // gh1 = h1 @ g1_whh^T + g1_bhh
        gemm(H1, H_DIM, g1_whh, H_DIM, g1_bhh, TA, G3, NROW, G3, H_DIM);
        gate_kernel<<<(NROW * H_DIM) / 256, 256>>>(
            CP, PP + (size_t)s * NROW * G3, TA, H1, nullptr);
        // gi2 = h1' @ g2_wih^T + g2_bih ; gh2 = h2 @ g2_whh^T + g2_bhh
        gemm(H1, H_DIM, g2_wih, H_DIM, g2_bih, TA, G3, NROW, G3, H_DIM);
        gemm(H2, H_DIM, g2_whh, H_DIM, g2_bhh, TB, G3, NROW, G3, H_DIM);
        gate_kernel<<<(NROW * H_DIM) / 256, 256>>>(
            TA, nullptr, TB, H2, HA + (size_t)s * NROW * H_DIM);
    }

    // ---- batched output projection + scatter ----
    gemm(HA, H_DIM, fco_w, H_DIM, fco_b, Y, D_DIM, TROW, D_DIM, H_DIM);
    scatter_out<<<(TROW * D_DIM + 255) / 256, 256>>>(Y, out);
}

// round 2
// speedup vs baseline: 1.5468x; 1.5468x over previous
#include <cuda_runtime.h>
#include <cstdint>
#include <cstddef>

// Problem dims (fixed by the dataset)
#define E_DIM 16
#define B_DIM 128
#define C_DIM 512
#define H_DIM 1024
#define D_DIM 130
#define DPAD  132            // D padded to mult of 4 (16B rows)
#define S_DIM 16
#define NROW  2048           // E*B
#define G3    3072           // 3*H
#define TROW  32768          // S*NROW
#define OUT_T 256            // E*S_DIM

// ---------------- scratch (static device globals; no allocation) -------------
__device__ __align__(16) float g_H1[NROW * H_DIM];
__device__ __align__(16) float g_H2[NROW * H_DIM];
__device__ __align__(16) float g_TA[NROW * G3];
__device__ __align__(16) float g_TB[NROW * G3];
__device__ __align__(16) float g_CP[NROW * G3];
__device__ __align__(16) float g_T0[NROW * 2 * H_DIM];
__device__ __align__(16) float g_PREV[(size_t)S_DIM * NROW * DPAD];
__device__ __align__(16) float g_PP[(size_t)S_DIM * NROW * G3];
__device__ __align__(16) float g_HA[(size_t)S_DIM * NROW * H_DIM];
__device__ __align__(16) float g_Y[(size_t)TROW * D_DIM];
__device__ __align__(16) float g_W1C[G3 * C_DIM];   // g1_wih[:, :C] repacked
__device__ __align__(16) float g_W1P[G3 * DPAD];    // g1_wih[:, C:] repacked+padded

// ---------------- TF32 helpers ----------------------------------------------
__device__ __forceinline__ float f2tf32(float x) {
    unsigned r;
    asm("cvt.rna.tf32.f32 %0, %1;" : "=r"(r) : "f"(x));
    return __uint_as_float(r);
}

__device__ __forceinline__ void mma_tf32(float d[4], const unsigned a[4],
                                         const unsigned b[2]) {
    asm volatile(
        "mma.sync.aligned.m16n8k8.row.col.f32.tf32.tf32.f32 "
        "{%0,%1,%2,%3}, {%4,%5,%6,%7}, {%8,%9}, {%0,%1,%2,%3};\n"
        : "+f"(d[0]), "+f"(d[1]), "+f"(d[2]), "+f"(d[3])
        : "r"(a[0]), "r"(a[1]), "r"(a[2]), "r"(a[3]),
          "r"(b[0]), "r"(b[1]));
}

// ---------------- TN GEMM, register double-buffered, batched via blockIdx.z --
// C[M,N] = A[M,K] * B[N,K]^T (+bias[n]).  BM=BN=128, BK=16, 256 thr, 8 warps.
#define BM 128
#define BN 128
#define BK 16
#define SROW 20            // BK + 4 pad: conflict-free fragment LDS
#define ASZ (BM * SROW)

template <bool HAS_BIAS>
__global__ __launch_bounds__(256, 2) void gemm_tn(
    const float* __restrict__ A0, const float* __restrict__ A1, int lda,
    const float* __restrict__ B0, const float* __restrict__ B1, int ldb,
    const float* __restrict__ bias0, const float* __restrict__ bias1,
    float* __restrict__ C0, float* __restrict__ C1, int ldc,
    int M, int N, int K)
{
    __shared__ __align__(16) float sm[2 * 2 * ASZ];

    const float* A    = blockIdx.z ? A1 : A0;
    const float* B    = blockIdx.z ? B1 : B0;
    const float* bias = blockIdx.z ? bias1 : bias0;
    float*       C    = blockIdx.z ? C1 : C0;

    const int tid  = threadIdx.x;
    const int lane = tid & 31;
    const int warp = tid >> 5;
    const int wm   = (warp & 1) * 64;
    const int wn   = (warp >> 1) * 32;
    const int g    = lane >> 2;
    const int tg   = lane & 3;
    const int bm0  = blockIdx.y * BM;
    const int bn0  = blockIdx.x * BN;

    float acc[4][4][4];
#pragma unroll
    for (int mi = 0; mi < 4; mi++)
#pragma unroll
        for (int ni = 0; ni < 4; ni++)
#pragma unroll
            for (int f = 0; f < 4; f++) acc[mi][ni][f] = 0.f;

    const int KT = (K + BK - 1) / BK;
    float4 ra[2], rb[2];
    const float4 z4 = make_float4(0.f, 0.f, 0.f, 0.f);

    // -------- load tile kt into registers --------
#define LOAD_TILE(kt)                                                         \
    {                                                                         \
        _Pragma("unroll") for (int i = 0; i < 2; i++) {                       \
            int f = i * 256 + tid;                                            \
            int r = f >> 2, cg = f & 3;                                       \
            int gc = (kt) * BK + cg * 4;                                      \
            ra[i] = (gc < K)                                                  \
                ? *(const float4*)(A + (size_t)(bm0 + r) * lda + gc) : z4;    \
            int gr = bn0 + r;                                                 \
            rb[i] = (gc < K && gr < N)                                        \
                ? *(const float4*)(B + (size_t)gr * ldb + gc) : z4;           \
        }                                                                     \
    }

    // -------- convert + store registers to smem stage st --------
#define STS_TILE(st)                                                          \
    {                                                                         \
        float* As = sm + (st) * 2 * ASZ;                                      \
        float* Bs = As + ASZ;                                                 \
        _Pragma("unroll") for (int i = 0; i < 2; i++) {                       \
            int f = i * 256 + tid;                                            \
            int r = f >> 2, cg = f & 3;                                       \
            float4 a = ra[i], b = rb[i];                                      \
            a.x = f2tf32(a.x); a.y = f2tf32(a.y);                             \
            a.z = f2tf32(a.z); a.w = f2tf32(a.w);                             \
            b.x = f2tf32(b.x); b.y = f2tf32(b.y);                             \
            b.z = f2tf32(b.z); b.w = f2tf32(b.w);                             \
            *(float4*)(As + r * SROW + cg * 4) = a;                           \
            *(float4*)(Bs + r * SROW + cg * 4) = b;                           \
        }                                                                     \
    }

    // -------- compute on smem stage st --------
#define COMP_TILE(st)                                                         \
    {                                                                         \
        const float* As = sm + (st) * 2 * ASZ;                                \
        const float* Bs = As + ASZ;                                           \
        _Pragma("unroll") for (int ks = 0; ks < 2; ks++) {                    \
            const int k0 = ks * 8;                                            \
            unsigned af[4][4], bf[4][2];                                      \
            _Pragma("unroll") for (int mi = 0; mi < 4; mi++) {                \
                const int rbase = wm + mi * 16;                               \
                af[mi][0] = __float_as_uint(As[(rbase + g) * SROW + k0 + tg]);       \
                af[mi][1] = __float_as_uint(As[(rbase + g + 8) * SROW + k0 + tg]);   \
                af[mi][2] = __float_as_uint(As[(rbase + g) * SROW + k0 + tg + 4]);   \
                af[mi][3] = __float_as_uint(As[(rbase + g + 8) * SROW + k0 + tg + 4]);\
            }                                                                 \
            _Pragma("unroll") for (int ni = 0; ni < 4; ni++) {                \
                const int nb = wn + ni * 8;                                   \
                bf[ni][0] = __float_as_uint(Bs[(nb + g) * SROW + k0 + tg]);      \
                bf[ni][1] = __float_as_uint(Bs[(nb + g) * SROW + k0 + tg + 4]);  \
            }                                                                 \
            _Pragma("unroll") for (int mi = 0; mi < 4; mi++)                  \
                _Pragma("unroll") for (int ni = 0; ni < 4; ni++)              \
                    mma_tf32(acc[mi][ni], af[mi], bf[ni]);                    \
        }                                                                     \
    }

    LOAD_TILE(0);
    STS_TILE(0);
    __syncthreads();
    int cur = 0;
    for (int kt = 1; kt < KT; kt++) {
        LOAD_TILE(kt);
        COMP_TILE(cur);
        STS_TILE(cur ^ 1);
        __syncthreads();
        cur ^= 1;
    }
    COMP_TILE(cur);

#undef LOAD_TILE
#undef STS_TILE
#undef COMP_TILE

    // -------- epilogue --------
#pragma unroll
    for (int mi = 0; mi < 4; mi++) {
        const int r0 = bm0 + wm + mi * 16 + g;   // M is always a mult of 128
#pragma unroll
        for (int ni = 0; ni < 4; ni++) {
            const int c0 = bn0 + wn + ni * 8 + 2 * tg;
            float b0 = 0.f, b1 = 0.f;
            if (HAS_BIAS) {
                if (c0 < N)     b0 = bias[c0];
                if (c0 + 1 < N) b1 = bias[c0 + 1];
            }
            if (c0 < N)     C[(size_t)r0 * ldc + c0]           = acc[mi][ni][0] + b0;
            if (c0 + 1 < N) C[(size_t)r0 * ldc + c0 + 1]       = acc[mi][ni][1] + b1;
            if (c0 < N)     C[(size_t)(r0 + 8) * ldc + c0]     = acc[mi][ni][2] + b0;
            if (c0 + 1 < N) C[(size_t)(r0 + 8) * ldc + c0 + 1] = acc[mi][ni][3] + b1;
        }
    }
}

// ---------------- elementwise kernels (float4) -------------------------------
__device__ __forceinline__ float sigf(float x) {
    return 1.f / (1.f + __expf(-x));
}

// gi = gi1 (+gi2); h' = (1-z)*n + z*h. One float4 = 4 hidden units.
template <bool HAS_GI2, bool HAS_COPY>
__global__ void gate_kernel(const float4* __restrict__ gi1,
                            const float4* __restrict__ gi2,
                            const float4* __restrict__ gh,
                            float4* __restrict__ h,
                            float4* __restrict__ hcopy)
{
    int v = blockIdx.x * blockDim.x + threadIdx.x;   // NROW*H/4 threads
    int m = v >> 8, q = v & 255;                     // H/4 = 256
    int base = m * 768 + q;                          // G3/4 = 768
    float4 ir = gi1[base], iz = gi1[base + 256], in = gi1[base + 512];
    if (HAS_GI2) {
        float4 a = gi2[base], b = gi2[base + 256], c = gi2[base + 512];
        ir.x += a.x; ir.y += a.y; ir.z += a.z; ir.w += a.w;
        iz.x += b.x; iz.y += b.y; iz.z += b.z; iz.w += b.w;
        in.x += c.x; in.y += c.y; in.z += c.z; in.w += c.w;
    }
    float4 hr = gh[base], hz = gh[base + 256], hn = gh[base + 512];
    float4 hv = h[v];
    float4 o;
    {
        float r = sigf(ir.x + hr.x), z = sigf(iz.x + hz.x);
        float n = tanhf(in.x + r * hn.x);
        o.x = (1.f - z) * n + z * hv.x;
    }
    {
        float r = sigf(ir.y + hr.y), z = sigf(iz.y + hz.y);
        float n = tanhf(in.y + r * hn.y);
        o.y = (1.f - z) * n + z * hv.y;
    }
    {
        float r = sigf(ir.z + hr.z), z = sigf(iz.z + hz.z);
        float n = tanhf(in.z + r * hn.z);
        o.z = (1.f - z) * n + z * hv.z;
    }
    {
        float r = sigf(ir.w + hr.w), z = sigf(iz.w + hz.w);
        float n = tanhf(in.w + r * hn.w);
        o.w = (1.f - z) * n + z * hv.w;
    }
    h[v] = o;
    if (HAS_COPY) hcopy[v] = o;
}

__global__ void init_tanh(const float4* __restrict__ t0,
                          float4* __restrict__ h1, float4* __restrict__ h2)
{
    int v = blockIdx.x * blockDim.x + threadIdx.x;   // NROW*H/4
    int m = v >> 8, q = v & 255;
    float4 a = t0[m * 512 + q];           // 2H/4 = 512
    float4 b = t0[m * 512 + 256 + q];
    a.x = tanhf(a.x); a.y = tanhf(a.y); a.z = tanhf(a.z); a.w = tanhf(a.w);
    b.x = tanhf(b.x); b.y = tanhf(b.y); b.z = tanhf(b.z); b.w = tanhf(b.w);
    h1[v] = a;
    h2[v] = b;
}

// PREV[s, e*B+b, d] (stride DPAD) = (t==0) ? 0 : target[b, t-1, d], t = e*S+s
__global__ void pack_prev(const float* __restrict__ target,
                          float* __restrict__ prev)
{
    int idx = blockIdx.x * blockDim.x + threadIdx.x;
    if (idx >= S_DIM * NROW * DPAD) return;
    int d = idx % DPAD;
    int r = (idx / DPAD) % NROW;
    int s = idx / (DPAD * NROW);
    int e = r >> 7, b = r & 127;
    int t = e * S_DIM + s;
    float val = 0.f;
    if (d < D_DIM && t != 0)
        val = target[((size_t)b * OUT_T + (t - 1)) * D_DIM + d];
    prev[idx] = val;
}

// repack g1_wih (row stride C+D=642) into W1C [3072x512] and W1P [3072x132]
__global__ void repack_w1(const float* __restrict__ w,
                          float* __restrict__ w1c, float* __restrict__ w1p)
{
    int idx = blockIdx.x * blockDim.x + threadIdx.x;
    const int T1 = G3 * C_DIM;
    const int T2 = G3 * DPAD;
    if (idx < T1) {
        int n = idx / C_DIM, k = idx % C_DIM;
        w1c[idx] = w[(size_t)n * (C_DIM + D_DIM) + k];
    } else if (idx < T1 + T2) {
        int j = idx - T1;
        int n = j / DPAD, k = j % DPAD;
        w1p[j] = (k < D_DIM) ? w[(size_t)n * (C_DIM + D_DIM) + C_DIM + k] : 0.f;
    }
}

// out[b, e*S+s, d] = Y[s*NROW + e*B + b, d]
__global__ void scatter_out(const float* __restrict__ y,
                            float* __restrict__ out)
{
    int idx = blockIdx.x * blockDim.x + threadIdx.x;
    if (idx >= TROW * D_DIM) return;
    int d = idx % D_DIM;
    int m = idx / D_DIM;
    int s = m >> 11;
    int r = m & 2047;
    int e = r >> 7, b = r & 127;
    out[((size_t)b * OUT_T + e * S_DIM + s) * D_DIM + d] = y[idx];
}

// ---------------- launch helpers ---------------------------------------------
static inline void gemm1(const float* A, int lda, const float* B, int ldb,
                         const float* bias, float* C, int ldc,
                         int M, int N, int K)
{
    dim3 grid((N + BN - 1) / BN, (M + BM - 1) / BM, 1);
    if (bias)
        gemm_tn<true><<<grid, 256>>>(A, A, lda, B, B, ldb, bias, bias,
                                     C, C, ldc, M, N, K);
    else
        gemm_tn<false><<<grid, 256>>>(A, A, lda, B, B, ldb, nullptr, nullptr,
                                      C, C, ldc, M, N, K);
}

static inline void gemm2(const float* A0, const float* A1, int lda,
                         const float* B0, const float* B1, int ldb,
                         const float* b0, const float* b1,
                         float* C0, float* C1, int ldc,
                         int M, int N, int K)
{
    dim3 grid((N + BN - 1) / BN, (M + BM - 1) / BM, 2);
    gemm_tn<true><<<grid, 256>>>(A0, A1, lda, B0, B1, ldb, b0, b1,
                                 C0, C1, ldc, M, N, K);
}

extern "C" void kernel_launch(void* const* d_in, const int* in_sizes, int n_in,
                              void* d_out, int out_size)
{
    const float* c      = (const float*)d_in[0];
    const float* target = (const float*)d_in[1];
    int base = (n_in >= 16) ? 4 : 2;
    const float* fc_init_w = (const float*)d_in[base + 0];
    const float* fc_init_b = (const float*)d_in[base + 1];
    const float* g1_wih    = (const float*)d_in[base + 2];
    const float* g1_whh    = (const float*)d_in[base + 3];
    const float* g1_bih    = (const float*)d_in[base + 4];
    const float* g1_bhh    = (const float*)d_in[base + 5];
    const float* g2_wih    = (const float*)d_in[base + 6];
    const float* g2_whh    = (const float*)d_in[base + 7];
    const float* g2_bih    = (const float*)d_in[base + 8];
    const float* g2_bhh    = (const float*)d_in[base + 9];
    const float* fco_w     = (const float*)d_in[base + 10];
    const float* fco_b     = (const float*)d_in[base + 11];
    float* out = (float*)d_out;

    float *H1, *H2, *TA, *TB, *CP, *T0, *PV, *PP, *HA, *Y, *W1C, *W1P;
    cudaGetSymbolAddress((void**)&H1, g_H1);
    cudaGetSymbolAddress((void**)&H2, g_H2);
    cudaGetSymbolAddress((void**)&TA, g_TA);
    cudaGetSymbolAddress((void**)&TB, g_TB);
    cudaGetSymbolAddress((void**)&CP, g_CP);
    cudaGetSymbolAddress((void**)&T0, g_T0);
    cudaGetSymbolAddress((void**)&PV, g_PREV);
    cudaGetSymbolAddress((void**)&PP, g_PP);
    cudaGetSymbolAddress((void**)&HA, g_HA);
    cudaGetSymbolAddress((void**)&Y,  g_Y);
    cudaGetSymbolAddress((void**)&W1C, g_W1C);
    cudaGetSymbolAddress((void**)&W1P, g_W1P);

    // ---- precompute (non-recurrent) ----
    repack_w1<<<(G3 * (C_DIM + DPAD) + 255) / 256, 256>>>(g1_wih, W1C, W1P);
    pack_prev<<<(S_DIM * NROW * DPAD + 255) / 256, 256>>>(target, PV);

    // cpart = cflat @ W1C^T + g1_bih        [2048 x 3072]
    gemm1(c, C_DIM, W1C, C_DIM, g1_bih, CP, G3, NROW, G3, C_DIM);
    // prevpart[s] = PREV[s] @ W1P^T         [32768 x 3072]
    gemm1(PV, DPAD, W1P, DPAD, nullptr, PP, G3, TROW, G3, DPAD);
    // t0 = c @ fc_init_w^T + fc_init_b      [2048 x 2048]
    gemm1(c, C_DIM, fc_init_w, C_DIM, fc_init_b, T0, 2 * H_DIM,
          NROW, 2 * H_DIM, C_DIM);
    init_tanh<<<(NROW * H_DIM / 4) / 256, 256>>>(
        (const float4*)T0, (float4*)H1, (float4*)H2);

    // ---- recurrent loop ----
    for (int s = 0; s < S_DIM; s++) {
        // gh1 = h1 @ g1_whh^T + g1_bhh ; gh2 = h2 @ g2_whh^T + g2_bhh (batched)
        gemm2(H1, H2, H_DIM, g1_whh, g2_whh, H_DIM, g1_bhh, g2_bhh,
              TA, TB, G3, NROW, G3, H_DIM);
        // gate1: h1' = GRU(cp+pp[s], gh1, h1)
        gate_kernel<true, false><<<(NROW * H_DIM / 4) / 256, 256>>>(
            (const float4*)CP, (const float4*)(PP + (size_t)s * NROW * G3),
            (const float4*)TA, (float4*)H1, nullptr);
        // gi2 = h1' @ g2_wih^T + g2_bih
        gemm1(H1, H_DIM, g2_wih, H_DIM, g2_bih, TA, G3, NROW, G3, H_DIM);
        // gate2: h2' = GRU(gi2, gh2, h2); also save to history
        gate_kernel<false, true><<<(NROW * H_DIM / 4) / 256, 256>>>(
            (const float4*)TA, nullptr, (const float4*)TB,
            (float4*)H2, (float4*)(HA + (size_t)s * NROW * H_DIM));
    }

    // ---- batched output projection + scatter ----
    gemm1(HA, H_DIM, fco_w, H_DIM, fco_b, Y, D_DIM, TROW, D_DIM, H_DIM);
    scatter_out<<<(TROW * D_DIM + 255) / 256, 256>>>(Y, out);
}